// round 1
// baseline (speedup 1.0000x reference)
#include <cuda_runtime.h>
#include <math.h>

#define BATCH 16
#define CINC 64
#define HH 128
#define WW 128
#define HW 16384
#define NCLS 80
#define KTOP 100

// ---------------- device scratch (no runtime allocation allowed) ----------------
__device__ float g_feat[BATCH * 192 * HW];   // relu(conv3x3) for all 3 branches: [b][192][h][w]
__device__ float g_cls [BATCH * NCLS * HW];  // sigmoid cls map
__device__ float g_score[BATCH * HW];        // peak-masked max score per pixel
__device__ int   g_cat  [BATCH * HW];        // argmax class per pixel
__device__ float g_tscore[BATCH * KTOP];
__device__ int   g_tind  [BATCH * KTOP];

// =====================================================================
// Kernel 1: fused 3x3 conv (64 -> 192 = cls64|reg64|wh64) + bias + relu
// tile 16x16, halo 18x18 (all 64 cin in smem), 16-oc weight chunks in smem,
// each thread: 4 px (x) x 4 oc register block.
// =====================================================================
__global__ __launch_bounds__(256) void conv1_kernel(
    const float* __restrict__ x,
    const float* __restrict__ w_cls, const float* __restrict__ b_cls,
    const float* __restrict__ w_reg, const float* __restrict__ b_reg,
    const float* __restrict__ w_wh,  const float* __restrict__ b_wh)
{
    extern __shared__ float sm[];
    float* s_in = sm;            // 64 * 18 * 18 = 20736 floats
    float* s_w  = sm + 20736;    // 16 * 576     = 9216 floats

    const int tx = blockIdx.x, ty = blockIdx.y, b = blockIdx.z;
    const int ox = tx * 16, oy = ty * 16;
    const int tid = threadIdx.x;
    const float* xb = x + (size_t)b * CINC * HW;

    // stage input tile (with zero 'SAME' padding)
    for (int e = tid; e < 64 * 324; e += 256) {
        int c   = e / 324;
        int rem = e - c * 324;
        int iy  = rem / 18;
        int ix  = rem - iy * 18;
        int gy = oy + iy - 1, gx = ox + ix - 1;
        float v = 0.f;
        if (gy >= 0 && gy < HH && gx >= 0 && gx < WW)
            v = xb[c * HW + gy * WW + gx];
        s_in[e] = v;
    }

    const int ocg = tid >> 6;          // 0..3 : oc sub-group
    const int r   = tid & 63;
    const int ly  = r >> 2;            // 0..15
    const int lx0 = (r & 3) * 4;       // 0,4,8,12

    const float* wptrs[3] = {w_cls, w_reg, w_wh};
    const float* bptrs[3] = {b_cls, b_reg, b_wh};
    float* fout = g_feat + (size_t)b * 192 * HW;

    for (int chunk = 0; chunk < 12; chunk++) {
        const int oc_base = chunk * 16;
        const int branch  = oc_base >> 6;
        const float* wp   = wptrs[branch];

        __syncthreads();  // covers input staging (first iter) + prev chunk compute
        for (int e = tid; e < 16 * 576; e += 256) {
            int o   = e / 576;
            int rem = e - o * 576;
            s_w[e] = wp[((oc_base + o) & 63) * 576 + rem];
        }
        __syncthreads();

        float acc[4][4];
        #pragma unroll
        for (int o = 0; o < 4; o++)
            #pragma unroll
            for (int p = 0; p < 4; p++) acc[o][p] = 0.f;

        for (int cin = 0; cin < 64; cin++) {
            const float* si = s_in + cin * 324;
            const float* sw = s_w + (ocg * 4) * 576 + cin * 9;
            #pragma unroll
            for (int ky = 0; ky < 3; ky++) {
                float in6[6];
                const float* row = si + (ly + ky) * 18 + lx0;
                #pragma unroll
                for (int i = 0; i < 6; i++) in6[i] = row[i];
                #pragma unroll
                for (int kx = 0; kx < 3; kx++) {
                    #pragma unroll
                    for (int o = 0; o < 4; o++) {
                        float wv = sw[o * 576 + ky * 3 + kx];
                        #pragma unroll
                        for (int p = 0; p < 4; p++)
                            acc[o][p] = fmaf(wv, in6[p + kx], acc[o][p]);
                    }
                }
            }
        }

        // bias + relu + store
        #pragma unroll
        for (int o = 0; o < 4; o++) {
            int oc = oc_base + ocg * 4 + o;
            float bias = bptrs[branch][oc & 63];
            float* op = fout + (size_t)oc * HW + (oy + ly) * WW + ox + lx0;
            #pragma unroll
            for (int p = 0; p < 4; p++) {
                float v = acc[o][p] + bias;
                op[p] = v > 0.f ? v : 0.f;
            }
        }
    }
}

// =====================================================================
// Kernel 2: 1x1 conv (feat[0:64] -> 80) + sigmoid -> g_cls
// thread = one pixel, feat channels cached in registers
// =====================================================================
__global__ __launch_bounds__(256) void conv_cls_kernel(
    const float* __restrict__ w2, const float* __restrict__ b2)
{
    __shared__ float sw[NCLS * 64];
    __shared__ float sb[NCLS];
    int tid = threadIdx.x;
    for (int e = tid; e < NCLS * 64; e += 256) sw[e] = w2[e];
    if (tid < NCLS) sb[tid] = b2[tid];
    __syncthreads();

    int g = blockIdx.x * 256 + tid;     // 0 .. B*HW-1
    int b = g >> 14;
    int p = g & (HW - 1);

    const float* fp = g_feat + (size_t)b * 192 * HW + p;
    float f[64];
    #pragma unroll
    for (int c = 0; c < 64; c++) f[c] = fp[c * HW];

    float* outp = g_cls + (size_t)b * NCLS * HW + p;
    for (int oc = 0; oc < NCLS; oc++) {
        float a = sb[oc];
        const float* w = sw + oc * 64;
        #pragma unroll
        for (int c = 0; c < 64; c++) a = fmaf(w[c], f[c], a);
        outp[oc * HW] = 1.f / (1.f + expf(-a));
    }
}

// =====================================================================
// Kernel 3: 3x3 peak suppression + per-pixel max/argmax over 80 classes
// (pooled==cls  <=>  v is max of its 3x3 window; OOB = -inf)
// =====================================================================
__global__ __launch_bounds__(256) void peak_kernel()
{
    __shared__ float st[324];
    const int tx = blockIdx.x, ty = blockIdx.y, b = blockIdx.z;
    const int ox = tx * 16, oy = ty * 16;
    const int tid = threadIdx.x;
    const int lx = tid & 15, ly = tid >> 4;

    const float NEG = -1e30f;
    float best = -1.f;
    int cat = 0;
    const float* clsb = g_cls + (size_t)b * NCLS * HW;

    for (int c = 0; c < NCLS; c++) {
        __syncthreads();
        for (int e = tid; e < 324; e += 256) {
            int iy = e / 18, ix = e - iy * 18;
            int gy = oy + iy - 1, gx = ox + ix - 1;
            float v = NEG;
            if (gy >= 0 && gy < HH && gx >= 0 && gx < WW)
                v = clsb[c * HW + gy * WW + gx];
            st[e] = v;
        }
        __syncthreads();
        float v = st[(ly + 1) * 18 + lx + 1];
        float m = v;
        #pragma unroll
        for (int dy = 0; dy < 3; dy++)
            #pragma unroll
            for (int dx = 0; dx < 3; dx++)
                m = fmaxf(m, st[(ly + dy) * 18 + lx + dx]);
        float masked = (v == m) ? v : 0.f;
        if (masked > best) { best = masked; cat = c; }
    }
    int p = (oy + ly) * WW + ox + lx;
    g_score[b * HW + p] = best;
    g_cat[b * HW + p]   = cat;
}

// =====================================================================
// Kernel 4: per-batch top-100 via packed u64 keys (score || inverted index)
// matches lax.top_k (descending score, ties -> smaller index)
// =====================================================================
__global__ __launch_bounds__(1024) void topk_kernel()
{
    extern __shared__ unsigned long long skey[];   // 16384 keys
    __shared__ unsigned long long warpmax[32];
    const int b = blockIdx.x;
    const int tid = threadIdx.x;
    const float* s = g_score + b * HW;

    for (int j = tid; j < HW; j += 1024) {
        unsigned int u = __float_as_uint(s[j]);    // scores >= 0 -> bits monotone
        skey[j] = ((unsigned long long)u << 32) | (unsigned long long)(16384 - j);
    }
    __syncthreads();

    for (int k = 0; k < KTOP; k++) {
        unsigned long long m = 0ull;
        for (int j = tid; j < HW; j += 1024) {
            unsigned long long t = skey[j];
            m = (t > m) ? t : m;
        }
        #pragma unroll
        for (int off = 16; off > 0; off >>= 1) {
            unsigned long long t = __shfl_down_sync(0xffffffffu, m, off);
            m = (t > m) ? t : m;
        }
        if ((tid & 31) == 0) warpmax[tid >> 5] = m;
        __syncthreads();
        if (tid < 32) {
            m = warpmax[tid];
            #pragma unroll
            for (int off = 16; off > 0; off >>= 1) {
                unsigned long long t = __shfl_down_sync(0xffffffffu, m, off);
                m = (t > m) ? t : m;
            }
            if (tid == 0) {
                int p = 16384 - (int)(m & 0xFFFFull);
                g_tscore[b * KTOP + k] = __uint_as_float((unsigned int)(m >> 32));
                g_tind[b * KTOP + k]   = p;
                skey[p] = 0ull;
            }
        }
        __syncthreads();
    }
}

// =====================================================================
// Kernel 5: gather reg/wh (1x1 conv at 100 points), decode boxes, greedy NMS,
// write flattened (boxes, cats, scores, keep) as float32
// =====================================================================
__global__ __launch_bounds__(128) void final_kernel(
    const float* __restrict__ reg_w2, const float* __restrict__ reg_b2,
    const float* __restrict__ wh_w2,  const float* __restrict__ wh_b2,
    float* __restrict__ out)
{
    const int b = blockIdx.x;
    const int tid = threadIdx.x;
    __shared__ float bx[KTOP][4];
    __shared__ float barea[KTOP];
    __shared__ int keep[KTOP];

    float score = 0.f; int cat = 0;
    if (tid < KTOP) {
        int p = g_tind[b * KTOP + tid];
        score = g_tscore[b * KTOP + tid];
        cat   = g_cat[b * HW + p];
        const float* f = g_feat + (size_t)b * 192 * HW + p;
        float r0 = reg_b2[0], r1 = reg_b2[1];
        float w0 = wh_b2[0],  w1 = wh_b2[1];
        for (int i = 0; i < 64; i++) {
            float fr = f[(64 + i) * HW];
            r0 = fmaf(fr, reg_w2[i],      r0);
            r1 = fmaf(fr, reg_w2[64 + i], r1);
            float fw = f[(128 + i) * HW];
            w0 = fmaf(fw, wh_w2[i],      w0);
            w1 = fmaf(fw, wh_w2[64 + i], w1);
        }
        r0 = 1.f / (1.f + expf(-r0));
        r1 = 1.f / (1.f + expf(-r1));
        w0 = expf(w0);
        w1 = expf(w1);
        float cx = (float)(p & 127) + r0;   // gx = p % W
        float cy = (float)(p >> 7)  + r1;   // gy = p / W
        float x1 = (cx - w0 * 0.5f) * 4.f, y1 = (cy - w1 * 0.5f) * 4.f;
        float x2 = (cx + w0 * 0.5f) * 4.f, y2 = (cy + w1 * 0.5f) * 4.f;
        bx[tid][0] = x1; bx[tid][1] = y1; bx[tid][2] = x2; bx[tid][3] = y2;
        barea[tid] = (x2 - x1) * (y2 - y1);
        keep[tid] = (score > 0.2f) ? 1 : 0;
    }
    __syncthreads();

    for (int i = 0; i < KTOP - 1; i++) {
        if (tid < KTOP && tid > i && keep[i]) {
            float xx1 = fmaxf(bx[i][0], bx[tid][0]);
            float yy1 = fmaxf(bx[i][1], bx[tid][1]);
            float xx2 = fminf(bx[i][2], bx[tid][2]);
            float yy2 = fminf(bx[i][3], bx[tid][3]);
            float iw = fmaxf(xx2 - xx1, 0.f);
            float ih = fmaxf(yy2 - yy1, 0.f);
            float inter = iw * ih;
            float iou = inter / (barea[i] + barea[tid] - inter + 1e-9f);
            if (iou > 0.5f) keep[tid] = 0;
        }
        __syncthreads();
    }

    if (tid < KTOP) {
        int base = b * KTOP + tid;
        out[base * 4 + 0] = bx[tid][0];
        out[base * 4 + 1] = bx[tid][1];
        out[base * 4 + 2] = bx[tid][2];
        out[base * 4 + 3] = bx[tid][3];
        out[6400 + base] = (float)cat;
        out[8000 + base] = score;
        out[9600 + base] = keep[tid] ? 1.f : 0.f;
    }
}

// =====================================================================
extern "C" void kernel_launch(void* const* d_in, const int* in_sizes, int n_in,
                              void* d_out, int out_size)
{
    const float* x      = (const float*)d_in[0];
    const float* cls_w1 = (const float*)d_in[1];
    const float* cls_b1 = (const float*)d_in[2];
    const float* cls_w2 = (const float*)d_in[3];
    const float* cls_b2 = (const float*)d_in[4];
    const float* reg_w1 = (const float*)d_in[5];
    const float* reg_b1 = (const float*)d_in[6];
    const float* reg_w2 = (const float*)d_in[7];
    const float* reg_b2 = (const float*)d_in[8];
    const float* wh_w1  = (const float*)d_in[9];
    const float* wh_b1  = (const float*)d_in[10];
    const float* wh_w2  = (const float*)d_in[11];
    const float* wh_b2  = (const float*)d_in[12];
    float* out = (float*)d_out;

    cudaFuncSetAttribute(conv1_kernel, cudaFuncAttributeMaxDynamicSharedMemorySize,
                         (20736 + 9216) * 4);
    cudaFuncSetAttribute(topk_kernel, cudaFuncAttributeMaxDynamicSharedMemorySize,
                         HW * 8);

    conv1_kernel<<<dim3(8, 8, BATCH), 256, (20736 + 9216) * 4>>>(
        x, cls_w1, cls_b1, reg_w1, reg_b1, wh_w1, wh_b1);
    conv_cls_kernel<<<(BATCH * HW) / 256, 256>>>(cls_w2, cls_b2);
    peak_kernel<<<dim3(8, 8, BATCH), 256>>>();
    topk_kernel<<<BATCH, 1024, HW * 8>>>();
    final_kernel<<<BATCH, 128>>>(reg_w2, reg_b2, wh_w2, wh_b2, out);
}

// round 2
// speedup vs baseline: 3.2446x; 3.2446x over previous
#include <cuda_runtime.h>
#include <math.h>

#define BATCH 16
#define CINC 64
#define HH 128
#define WW 128
#define HW 16384
#define NCLS 80
#define KTOP 100

// ---------------- device scratch ----------------
__device__ float g_featc[BATCH * 64 * HW];   // relu(conv3x3) cls branch only
__device__ float g_cls  [BATCH * NCLS * HW]; // sigmoid cls map
__device__ float g_score[BATCH * HW];
__device__ int   g_cat  [BATCH * HW];
__device__ float g_tscore[BATCH * KTOP];
__device__ int   g_tind  [BATCH * KTOP];
__device__ float g_boxes[BATCH * KTOP * 4];

// ---------------- f32x2 helpers ----------------
__device__ __forceinline__ unsigned long long pk2(float lo, float hi) {
    unsigned long long r;
    asm("mov.b64 %0, {%1, %2};" : "=l"(r) : "r"(__float_as_uint(lo)), "r"(__float_as_uint(hi)));
    return r;
}
__device__ __forceinline__ unsigned long long dup2(float x) { return pk2(x, x); }
__device__ __forceinline__ unsigned long long fma2(unsigned long long a, unsigned long long b,
                                                   unsigned long long c) {
    unsigned long long d;
    asm("fma.rn.f32x2 %0, %1, %2, %3;" : "=l"(d) : "l"(a), "l"(b), "l"(c));
    return d;
}
__device__ __forceinline__ float2 upk(unsigned long long v) {
    unsigned int a, b;
    asm("mov.b64 {%0, %1}, %2;" : "=r"(a), "=r"(b) : "l"(v));
    return make_float2(__uint_as_float(a), __uint_as_float(b));
}

// =====================================================================
// Kernel 1: 3x3 conv (64 -> 64, cls branch only) + bias + relu, f32x2.
// 16x16 tile, 256 threads; thread = 8 px (x) x 4 oc (2 oc-pairs).
// s_in: 64 cin x 18 rows x stride 20 (16B aligned vec loads)
// s_w : [cin][k][36] (32 oc used, pad 36 for bank spread, 16B aligned)
// =====================================================================
#define SIN_WORDS (64 * 18 * 20)
#define SW_WORDS  (64 * 9 * 36)
#define CONV1_SMEM ((SIN_WORDS + SW_WORDS) * 4)

__global__ __launch_bounds__(256, 1) void conv1_kernel(
    const float* __restrict__ x,
    const float* __restrict__ w1, const float* __restrict__ b1)
{
    extern __shared__ float sm[];
    float* s_in = sm;
    float* s_w  = sm + SIN_WORDS;

    const int tx = blockIdx.x, ty = blockIdx.y, b = blockIdx.z;
    const int ox = tx * 16, oy = ty * 16;
    const int tid = threadIdx.x;
    const float* xb = x + (size_t)b * CINC * HW;

    // stage input tile (zero-padded halo), stride-20 rows
    for (int e = tid; e < 64 * 324; e += 256) {
        int c   = e / 324;
        int rem = e - c * 324;
        int iy  = rem / 18;
        int ix  = rem - iy * 18;
        int gy = oy + iy - 1, gx = ox + ix - 1;
        float v = 0.f;
        if (gy >= 0 && gy < HH && gx >= 0 && gx < WW)
            v = xb[c * HW + gy * WW + gx];
        s_in[c * 360 + iy * 20 + ix] = v;
    }

    const int ocg = tid >> 5;          // 0..7
    const int r   = tid & 31;
    const int ly  = r >> 1;            // 0..15
    const int lx0 = (r & 1) * 8;       // 0 or 8

    float* fout = g_featc + (size_t)b * 64 * HW;

    for (int chunk = 0; chunk < 2; chunk++) {
        const int oc_base = chunk * 32;
        __syncthreads();
        for (int e = tid; e < 32 * 576; e += 256) {
            int o   = e / 576;
            int rem = e - o * 576;
            s_w[rem * 36 + o] = w1[(oc_base + o) * 576 + rem];
        }
        __syncthreads();

        unsigned long long acc01[8], acc23[8];
        #pragma unroll
        for (int p = 0; p < 8; p++) { acc01[p] = 0ull; acc23[p] = 0ull; }

        for (int cin = 0; cin < 64; cin++) {
            const float* si  = s_in + cin * 360 + ly * 20 + lx0;
            const float* swc = s_w + cin * 9 * 36 + ocg * 4;
            #pragma unroll
            for (int ky = 0; ky < 3; ky++) {
                const float* row = si + ky * 20;
                float4 va = *(const float4*)(row);
                float4 vb = *(const float4*)(row + 4);
                float2 vc = *(const float2*)(row + 8);
                unsigned long long d[10];
                d[0]=dup2(va.x); d[1]=dup2(va.y); d[2]=dup2(va.z); d[3]=dup2(va.w);
                d[4]=dup2(vb.x); d[5]=dup2(vb.y); d[6]=dup2(vb.z); d[7]=dup2(vb.w);
                d[8]=dup2(vc.x); d[9]=dup2(vc.y);
                #pragma unroll
                for (int kx = 0; kx < 3; kx++) {
                    ulonglong2 wv = *(const ulonglong2*)(swc + (ky * 3 + kx) * 36);
                    #pragma unroll
                    for (int p = 0; p < 8; p++) {
                        acc01[p] = fma2(d[p + kx], wv.x, acc01[p]);
                        acc23[p] = fma2(d[p + kx], wv.y, acc23[p]);
                    }
                }
            }
        }

        // unpack, bias, relu, store (8 px per oc as 2x float4)
        float rr[4][8];
        #pragma unroll
        for (int p = 0; p < 8; p++) {
            float2 a = upk(acc01[p]);
            float2 c = upk(acc23[p]);
            rr[0][p] = a.x; rr[1][p] = a.y; rr[2][p] = c.x; rr[3][p] = c.y;
        }
        #pragma unroll
        for (int i = 0; i < 4; i++) {
            int oc = oc_base + ocg * 4 + i;
            float bias = b1[oc];
            float* op = fout + (size_t)oc * HW + (oy + ly) * WW + ox + lx0;
            float4 v0, v1;
            v0.x = fmaxf(rr[i][0] + bias, 0.f); v0.y = fmaxf(rr[i][1] + bias, 0.f);
            v0.z = fmaxf(rr[i][2] + bias, 0.f); v0.w = fmaxf(rr[i][3] + bias, 0.f);
            v1.x = fmaxf(rr[i][4] + bias, 0.f); v1.y = fmaxf(rr[i][5] + bias, 0.f);
            v1.z = fmaxf(rr[i][6] + bias, 0.f); v1.w = fmaxf(rr[i][7] + bias, 0.f);
            *(float4*)(op)     = v0;
            *(float4*)(op + 4) = v1;
        }
    }
}

// =====================================================================
// Kernel 2: 1x1 conv (64 -> 80) + sigmoid, f32x2 over oc-pairs.
// thread = 1 px; f[64] in regs; two halves of 20 oc-pairs.
// =====================================================================
__global__ __launch_bounds__(256) void conv_cls_kernel(
    const float* __restrict__ w2, const float* __restrict__ b2)
{
    __shared__ float sw[64 * 80];   // [c][oc]
    __shared__ float sb[NCLS];
    int tid = threadIdx.x;
    for (int e = tid; e < NCLS * 64; e += 256) {
        int oc = e / 64, c = e - oc * 64;
        sw[c * 80 + oc] = w2[e];
    }
    if (tid < NCLS) sb[tid] = b2[tid];
    __syncthreads();

    int g = blockIdx.x * 256 + tid;
    int b = g >> 14;
    int p = g & (HW - 1);

    const float* fp = g_featc + (size_t)b * 64 * HW + p;
    float f[64];
    #pragma unroll
    for (int c = 0; c < 64; c++) f[c] = fp[c * HW];

    float* outp = g_cls + (size_t)b * NCLS * HW + p;
    #pragma unroll
    for (int h = 0; h < 2; h++) {
        unsigned long long acc[20];
        #pragma unroll
        for (int i = 0; i < 20; i++) acc[i] = pk2(sb[h * 40 + 2 * i], sb[h * 40 + 2 * i + 1]);
        for (int c = 0; c < 64; c++) {
            unsigned long long ad = dup2(f[c]);
            const unsigned long long* wp =
                (const unsigned long long*)(sw + c * 80 + h * 40);
            #pragma unroll
            for (int i = 0; i < 20; i++) acc[i] = fma2(ad, wp[i], acc[i]);
        }
        #pragma unroll
        for (int i = 0; i < 20; i++) {
            float2 v = upk(acc[i]);
            int oc = h * 40 + 2 * i;
            outp[(size_t)oc * HW]       = 1.f / (1.f + expf(-v.x));
            outp[(size_t)(oc + 1) * HW] = 1.f / (1.f + expf(-v.y));
        }
    }
}

// =====================================================================
// Kernel 3: 3x3 peak suppression + max/argmax over classes. Row strips.
// block = 128 threads = one image row; double-buffered v3 row.
// =====================================================================
__global__ __launch_bounds__(128) void peak_kernel()
{
    __shared__ float v3buf[2][130];
    const int y = blockIdx.x, b = blockIdx.y;
    const int xx = threadIdx.x;
    const float NEG = -1e30f;

    if (xx == 0) {
        v3buf[0][0] = NEG; v3buf[0][129] = NEG;
        v3buf[1][0] = NEG; v3buf[1][129] = NEG;
    }

    float best = -1.f;
    int cat = 0;
    const float* base = g_cls + (size_t)b * NCLS * HW;

    for (int c = 0; c < NCLS; c++) {
        const float* pc = base + (size_t)c * HW + y * WW + xx;
        float mid = pc[0];
        float up  = (y > 0)      ? pc[-WW] : NEG;
        float dn  = (y < HH - 1) ? pc[WW]  : NEG;
        float v3 = fmaxf(mid, fmaxf(up, dn));
        float* buf = v3buf[c & 1];
        buf[xx + 1] = v3;
        __syncthreads();
        float pooled = fmaxf(buf[xx], fmaxf(buf[xx + 1], buf[xx + 2]));
        float masked = (mid == pooled) ? mid : 0.f;
        if (masked > best) { best = masked; cat = c; }
    }
    g_score[b * HW + y * WW + xx] = best;
    g_cat[b * HW + y * WW + xx]   = cat;
}

// =====================================================================
// Kernel 4: top-100 via 13-bit histogram radix-select, then exact
// selection on the small candidate set (packed u64 keys).
// =====================================================================
#define TOPK_SMEM (8192 * 4 + 1024 * 4 + HW * 8)
__global__ __launch_bounds__(1024) void topk_kernel()
{
    extern __shared__ int smi[];
    int* hist = smi;                                     // 8192
    int* suf  = smi + 8192;                              // 1024
    unsigned long long* cand = (unsigned long long*)(smi + 8192 + 1024);
    __shared__ int s_tstar, s_T, s_cnt;
    __shared__ unsigned long long warpmax[32];
    __shared__ unsigned long long s_m;

    const int b = blockIdx.x;
    const int tid = threadIdx.x;
    const float* s = g_score + b * HW;

    for (int i = tid; i < 8192; i += 1024) hist[i] = 0;
    if (tid == 0) s_cnt = 0;
    __syncthreads();

    for (int j = tid; j < HW; j += 1024) {
        unsigned int u = __float_as_uint(s[j]);          // scores >= 0
        atomicAdd(&hist[u >> 19], 1);
    }
    __syncthreads();

    int seg = 0;
    #pragma unroll
    for (int k = 0; k < 8; k++) seg += hist[tid * 8 + k];
    suf[tid] = seg;
    __syncthreads();
    for (int off = 1; off < 1024; off <<= 1) {
        int v = suf[tid];
        int add = (tid + off < 1024) ? suf[tid + off] : 0;
        __syncthreads();
        suf[tid] = v + add;
        __syncthreads();
    }
    if (suf[tid] >= KTOP && (tid == 1023 || suf[tid + 1] < KTOP)) s_tstar = tid;
    __syncthreads();
    if (tid == s_tstar) {
        int acc = (tid == 1023) ? 0 : suf[tid + 1];
        for (int bb = tid * 8 + 7; bb >= tid * 8; bb--) {
            acc += hist[bb];
            if (acc >= KTOP) { s_T = bb; break; }
        }
    }
    __syncthreads();
    const int T = s_T;

    for (int j = tid; j < HW; j += 1024) {
        unsigned int u = __float_as_uint(s[j]);
        if ((int)(u >> 19) >= T) {
            int pos = atomicAdd(&s_cnt, 1);
            cand[pos] = ((unsigned long long)u << 32) | (unsigned long long)(HW - j);
        }
    }
    __syncthreads();
    const int N = s_cnt;

    for (int k = 0; k < KTOP; k++) {
        unsigned long long m = 0ull;
        for (int i = tid; i < N; i += 1024) {
            unsigned long long t = cand[i];
            m = (t > m) ? t : m;
        }
        #pragma unroll
        for (int off = 16; off > 0; off >>= 1) {
            unsigned long long t = __shfl_down_sync(0xffffffffu, m, off);
            m = (t > m) ? t : m;
        }
        if ((tid & 31) == 0) warpmax[tid >> 5] = m;
        __syncthreads();
        if (tid < 32) {
            m = warpmax[tid];
            #pragma unroll
            for (int off = 16; off > 0; off >>= 1) {
                unsigned long long t = __shfl_down_sync(0xffffffffu, m, off);
                m = (t > m) ? t : m;
            }
            if (tid == 0) s_m = m;
        }
        __syncthreads();
        unsigned long long M = s_m;
        if (tid == 0) {
            g_tscore[b * KTOP + k] = __uint_as_float((unsigned int)(M >> 32));
            g_tind[b * KTOP + k]   = HW - (int)(M & 0xFFFFFFFFull);
        }
        for (int i = tid; i < N; i += 1024)
            if (cand[i] == M) cand[i] = 0ull;
        __syncthreads();
    }
}

// =====================================================================
// Kernel 5: recompute reg/wh 3x3 conv at the selected points, then the
// 1x1 heads + box decode. block = 128 threads (thread = 1 of 128 mid
// channels), 10 points per block. grid (10, B).
// =====================================================================
__global__ __launch_bounds__(128) void point_kernel(
    const float* __restrict__ x,
    const float* __restrict__ rw1, const float* __restrict__ rb1,
    const float* __restrict__ rw2, const float* __restrict__ rb2,
    const float* __restrict__ ww1, const float* __restrict__ wb1,
    const float* __restrict__ ww2, const float* __restrict__ wb2)
{
    __shared__ float sx[10][576];
    __shared__ int   sp[10];
    __shared__ float sfa[128][11];
    __shared__ float sres[10][4];

    const int g = blockIdx.x, b = blockIdx.y;
    const int tid = threadIdx.x;

    if (tid < 10) sp[tid] = g_tind[b * KTOP + g * 10 + tid];
    __syncthreads();

    for (int e = tid; e < 10 * 576; e += 128) {
        int pt = e / 576;
        int r  = e - pt * 576;
        int c  = r / 9;
        int k9 = r - c * 9;
        int dy = k9 / 3 - 1, dx = k9 % 3 - 1;
        int p = sp[pt];
        int gy = (p >> 7) + dy, gx = (p & 127) + dx;
        float v = 0.f;
        if (gy >= 0 && gy < HH && gx >= 0 && gx < WW)
            v = x[((size_t)b * CINC + c) * HW + gy * WW + gx];
        sx[pt][r] = v;
    }
    __syncthreads();

    const float* wrow = (tid < 64) ? (rw1 + tid * 576) : (ww1 + (tid - 64) * 576);
    float bias = (tid < 64) ? rb1[tid] : wb1[tid - 64];
    float acc[10];
    #pragma unroll
    for (int pt = 0; pt < 10; pt++) acc[pt] = bias;

    for (int j = 0; j < 576; j += 4) {
        float4 w4 = *(const float4*)(wrow + j);
        #pragma unroll
        for (int q = 0; q < 4; q++) {
            float w = (q == 0) ? w4.x : (q == 1) ? w4.y : (q == 2) ? w4.z : w4.w;
            #pragma unroll
            for (int pt = 0; pt < 10; pt++)
                acc[pt] = fmaf(w, sx[pt][j + q], acc[pt]);
        }
    }
    #pragma unroll
    for (int pt = 0; pt < 10; pt++) sfa[tid][pt] = fmaxf(acc[pt], 0.f);
    __syncthreads();

    if (tid < 40) {
        int pt = tid >> 2, o = tid & 3;
        float sv;
        if (o < 2) {
            sv = rb2[o];
            for (int i = 0; i < 64; i++) sv = fmaf(sfa[i][pt], rw2[o * 64 + i], sv);
            sv = 1.f / (1.f + expf(-sv));
        } else {
            int oo = o - 2;
            sv = wb2[oo];
            for (int i = 0; i < 64; i++) sv = fmaf(sfa[64 + i][pt], ww2[oo * 64 + i], sv);
            sv = expf(sv);
        }
        sres[pt][o] = sv;
    }
    __syncthreads();

    if (tid < 10) {
        int p = sp[tid];
        float cx = (float)(p & 127) + sres[tid][0];
        float cy = (float)(p >> 7)  + sres[tid][1];
        float wv = sres[tid][2], hv = sres[tid][3];
        int k = b * KTOP + g * 10 + tid;
        g_boxes[k * 4 + 0] = (cx - wv * 0.5f) * 4.f;
        g_boxes[k * 4 + 1] = (cy - hv * 0.5f) * 4.f;
        g_boxes[k * 4 + 2] = (cx + wv * 0.5f) * 4.f;
        g_boxes[k * 4 + 3] = (cy + hv * 0.5f) * 4.f;
    }
}

// =====================================================================
// Kernel 6: greedy NMS + output assembly
// =====================================================================
__global__ __launch_bounds__(128) void nms_kernel(float* __restrict__ out)
{
    const int b = blockIdx.x;
    const int tid = threadIdx.x;
    __shared__ float bx[KTOP][4];
    __shared__ float barea[KTOP];
    __shared__ int keep[KTOP];

    float score = 0.f; int cat = 0;
    if (tid < KTOP) {
        int k = b * KTOP + tid;
        score = g_tscore[k];
        cat   = g_cat[b * HW + g_tind[k]];
        float x1 = g_boxes[k * 4 + 0], y1 = g_boxes[k * 4 + 1];
        float x2 = g_boxes[k * 4 + 2], y2 = g_boxes[k * 4 + 3];
        bx[tid][0] = x1; bx[tid][1] = y1; bx[tid][2] = x2; bx[tid][3] = y2;
        barea[tid] = (x2 - x1) * (y2 - y1);
        keep[tid] = (score > 0.2f) ? 1 : 0;
    }
    __syncthreads();

    for (int i = 0; i < KTOP - 1; i++) {
        if (tid < KTOP && tid > i && keep[i]) {
            float xx1 = fmaxf(bx[i][0], bx[tid][0]);
            float yy1 = fmaxf(bx[i][1], bx[tid][1]);
            float xx2 = fminf(bx[i][2], bx[tid][2]);
            float yy2 = fminf(bx[i][3], bx[tid][3]);
            float iw = fmaxf(xx2 - xx1, 0.f);
            float ih = fmaxf(yy2 - yy1, 0.f);
            float inter = iw * ih;
            float iou = inter / (barea[i] + barea[tid] - inter + 1e-9f);
            if (iou > 0.5f) keep[tid] = 0;
        }
        __syncthreads();
    }

    if (tid < KTOP) {
        int base = b * KTOP + tid;
        out[base * 4 + 0] = bx[tid][0];
        out[base * 4 + 1] = bx[tid][1];
        out[base * 4 + 2] = bx[tid][2];
        out[base * 4 + 3] = bx[tid][3];
        out[6400 + base] = (float)cat;
        out[8000 + base] = score;
        out[9600 + base] = keep[tid] ? 1.f : 0.f;
    }
}

// =====================================================================
extern "C" void kernel_launch(void* const* d_in, const int* in_sizes, int n_in,
                              void* d_out, int out_size)
{
    const float* x      = (const float*)d_in[0];
    const float* cls_w1 = (const float*)d_in[1];
    const float* cls_b1 = (const float*)d_in[2];
    const float* cls_w2 = (const float*)d_in[3];
    const float* cls_b2 = (const float*)d_in[4];
    const float* reg_w1 = (const float*)d_in[5];
    const float* reg_b1 = (const float*)d_in[6];
    const float* reg_w2 = (const float*)d_in[7];
    const float* reg_b2 = (const float*)d_in[8];
    const float* wh_w1  = (const float*)d_in[9];
    const float* wh_b1  = (const float*)d_in[10];
    const float* wh_w2  = (const float*)d_in[11];
    const float* wh_b2  = (const float*)d_in[12];
    float* out = (float*)d_out;

    cudaFuncSetAttribute(conv1_kernel, cudaFuncAttributeMaxDynamicSharedMemorySize, CONV1_SMEM);
    cudaFuncSetAttribute(topk_kernel, cudaFuncAttributeMaxDynamicSharedMemorySize, TOPK_SMEM);

    conv1_kernel<<<dim3(8, 8, BATCH), 256, CONV1_SMEM>>>(x, cls_w1, cls_b1);
    conv_cls_kernel<<<(BATCH * HW) / 256, 256>>>(cls_w2, cls_b2);
    peak_kernel<<<dim3(HH, BATCH), 128>>>();
    topk_kernel<<<BATCH, 1024, TOPK_SMEM>>>();
    point_kernel<<<dim3(10, BATCH), 128>>>(x, reg_w1, reg_b1, reg_w2, reg_b2,
                                           wh_w1, wh_b1, wh_w2, wh_b2);
    nms_kernel<<<BATCH, 128>>>(out);
}

// round 3
// speedup vs baseline: 3.3878x; 1.0441x over previous
#include <cuda_runtime.h>
#include <math.h>

#define BATCH 16
#define CINC 64
#define HH 128
#define WW 128
#define HW 16384
#define NCLS 80
#define KTOP 100

// ---------------- device scratch ----------------
__device__ float g_featc[BATCH * 64 * HW];   // relu(conv3x3) cls branch only
__device__ float g_score[BATCH * HW];
__device__ int   g_cat  [BATCH * HW];
__device__ float g_tscore[BATCH * KTOP];
__device__ int   g_tind  [BATCH * KTOP];
__device__ float g_boxes[BATCH * KTOP * 4];

// ---------------- f32x2 helpers ----------------
__device__ __forceinline__ unsigned long long pk2(float lo, float hi) {
    unsigned long long r;
    asm("mov.b64 %0, {%1, %2};" : "=l"(r) : "r"(__float_as_uint(lo)), "r"(__float_as_uint(hi)));
    return r;
}
__device__ __forceinline__ unsigned long long dup2(float x) { return pk2(x, x); }
__device__ __forceinline__ unsigned long long fma2(unsigned long long a, unsigned long long b,
                                                   unsigned long long c) {
    unsigned long long d;
    asm("fma.rn.f32x2 %0, %1, %2, %3;" : "=l"(d) : "l"(a), "l"(b), "l"(c));
    return d;
}
__device__ __forceinline__ float2 upk(unsigned long long v) {
    unsigned int a, b;
    asm("mov.b64 {%0, %1}, %2;" : "=r"(a), "=r"(b) : "l"(v));
    return make_float2(__uint_as_float(a), __uint_as_float(b));
}

// =====================================================================
// Kernel 1: 3x3 conv (64 -> 64, cls branch only) + bias + relu, f32x2.
// =====================================================================
#define SIN_WORDS (64 * 18 * 20)
#define SW_WORDS  (64 * 9 * 36)
#define CONV1_SMEM ((SIN_WORDS + SW_WORDS) * 4)

__global__ __launch_bounds__(256, 1) void conv1_kernel(
    const float* __restrict__ x,
    const float* __restrict__ w1, const float* __restrict__ b1)
{
    extern __shared__ float sm[];
    float* s_in = sm;
    float* s_w  = sm + SIN_WORDS;

    const int tx = blockIdx.x, ty = blockIdx.y, b = blockIdx.z;
    const int ox = tx * 16, oy = ty * 16;
    const int tid = threadIdx.x;
    const float* xb = x + (size_t)b * CINC * HW;

    for (int e = tid; e < 64 * 324; e += 256) {
        int c   = e / 324;
        int rem = e - c * 324;
        int iy  = rem / 18;
        int ix  = rem - iy * 18;
        int gy = oy + iy - 1, gx = ox + ix - 1;
        float v = 0.f;
        if (gy >= 0 && gy < HH && gx >= 0 && gx < WW)
            v = xb[c * HW + gy * WW + gx];
        s_in[c * 360 + iy * 20 + ix] = v;
    }

    const int ocg = tid >> 5;
    const int r   = tid & 31;
    const int ly  = r >> 1;
    const int lx0 = (r & 1) * 8;

    float* fout = g_featc + (size_t)b * 64 * HW;

    for (int chunk = 0; chunk < 2; chunk++) {
        const int oc_base = chunk * 32;
        __syncthreads();
        for (int e = tid; e < 32 * 576; e += 256) {
            int o   = e / 576;
            int rem = e - o * 576;
            s_w[rem * 36 + o] = w1[(oc_base + o) * 576 + rem];
        }
        __syncthreads();

        unsigned long long acc01[8], acc23[8];
        #pragma unroll
        for (int p = 0; p < 8; p++) { acc01[p] = 0ull; acc23[p] = 0ull; }

        for (int cin = 0; cin < 64; cin++) {
            const float* si  = s_in + cin * 360 + ly * 20 + lx0;
            const float* swc = s_w + cin * 9 * 36 + ocg * 4;
            #pragma unroll
            for (int ky = 0; ky < 3; ky++) {
                const float* row = si + ky * 20;
                float4 va = *(const float4*)(row);
                float4 vb = *(const float4*)(row + 4);
                float2 vc = *(const float2*)(row + 8);
                unsigned long long d[10];
                d[0]=dup2(va.x); d[1]=dup2(va.y); d[2]=dup2(va.z); d[3]=dup2(va.w);
                d[4]=dup2(vb.x); d[5]=dup2(vb.y); d[6]=dup2(vb.z); d[7]=dup2(vb.w);
                d[8]=dup2(vc.x); d[9]=dup2(vc.y);
                #pragma unroll
                for (int kx = 0; kx < 3; kx++) {
                    ulonglong2 wv = *(const ulonglong2*)(swc + (ky * 3 + kx) * 36);
                    #pragma unroll
                    for (int p = 0; p < 8; p++) {
                        acc01[p] = fma2(d[p + kx], wv.x, acc01[p]);
                        acc23[p] = fma2(d[p + kx], wv.y, acc23[p]);
                    }
                }
            }
        }

        float rr[4][8];
        #pragma unroll
        for (int p = 0; p < 8; p++) {
            float2 a = upk(acc01[p]);
            float2 c = upk(acc23[p]);
            rr[0][p] = a.x; rr[1][p] = a.y; rr[2][p] = c.x; rr[3][p] = c.y;
        }
        #pragma unroll
        for (int i = 0; i < 4; i++) {
            int oc = oc_base + ocg * 4 + i;
            float bias = b1[oc];
            float* op = fout + (size_t)oc * HW + (oy + ly) * WW + ox + lx0;
            float4 v0, v1;
            v0.x = fmaxf(rr[i][0] + bias, 0.f); v0.y = fmaxf(rr[i][1] + bias, 0.f);
            v0.z = fmaxf(rr[i][2] + bias, 0.f); v0.w = fmaxf(rr[i][3] + bias, 0.f);
            v1.x = fmaxf(rr[i][4] + bias, 0.f); v1.y = fmaxf(rr[i][5] + bias, 0.f);
            v1.z = fmaxf(rr[i][6] + bias, 0.f); v1.w = fmaxf(rr[i][7] + bias, 0.f);
            *(float4*)(op)     = v0;
            *(float4*)(op + 4) = v1;
        }
    }
}

// =====================================================================
// Kernel 2 (fused): 1x1 conv (64->80) + sigmoid + 3x3 peak suppression
// + max/argmax over classes, all in one tile pass. g_cls never exists.
// 352 threads; thread<324 owns one halo px with feat cached in regs as
// 32 channel-pairs; 40 rounds x 2 classes. Inner 256 threads pool.
// =====================================================================
__global__ __launch_bounds__(352, 2) void clspeak_kernel(
    const float* __restrict__ w2, const float* __restrict__ b2)
{
    __shared__ float s_w[80 * 64];
    __shared__ float s_b[80];
    __shared__ float s_c0[324];
    __shared__ float s_c1[324];

    const int tx = blockIdx.x, ty = blockIdx.y, b = blockIdx.z;
    const int ox = tx * 16, oy = ty * 16;
    const int tid = threadIdx.x;
    const float NEG = -1e30f;

    for (int e = tid; e < 80 * 64; e += 352) s_w[e] = w2[e];
    if (tid < 80) s_b[tid] = b2[tid];

    // register-cache feat halo px as channel pairs
    unsigned long long fd[32];
    bool inimg = false;
    if (tid < 324) {
        int iy = tid / 18, ix = tid - iy * 18;
        int gy = oy + iy - 1, gx = ox + ix - 1;
        inimg = (gy >= 0 && gy < HH && gx >= 0 && gx < WW);
        const float* fp = g_featc + (size_t)b * 64 * HW + gy * WW + gx;
        #pragma unroll
        for (int i = 0; i < 32; i++) {
            float a = inimg ? fp[(2 * i) * HW]     : 0.f;
            float c = inimg ? fp[(2 * i + 1) * HW] : 0.f;
            fd[i] = pk2(a, c);
        }
    }
    __syncthreads();

    const int py = (tid >> 4) + 1, px = (tid & 15) + 1;  // inner pool coords
    const int pp = py * 18 + px;
    float best = -1.f;
    int cat = 0;

    for (int cp = 0; cp < 40; cp++) {
        const int c0 = 2 * cp, c1 = 2 * cp + 1;
        if (tid < 324) {
            unsigned long long a0 = 0ull, a1 = 0ull;
            const ulonglong2* w0 = (const ulonglong2*)(s_w + c0 * 64);
            const ulonglong2* w1 = (const ulonglong2*)(s_w + c1 * 64);
            #pragma unroll
            for (int i = 0; i < 16; i++) {
                ulonglong2 wa = w0[i];
                ulonglong2 wb = w1[i];
                a0 = fma2(fd[2 * i],     wa.x, a0);
                a0 = fma2(fd[2 * i + 1], wa.y, a0);
                a1 = fma2(fd[2 * i],     wb.x, a1);
                a1 = fma2(fd[2 * i + 1], wb.y, a1);
            }
            float2 u0 = upk(a0), u1 = upk(a1);
            float v0 = u0.x + u0.y + s_b[c0];
            float v1 = u1.x + u1.y + s_b[c1];
            v0 = 1.f / (1.f + expf(-v0));
            v1 = 1.f / (1.f + expf(-v1));
            if (!inimg) { v0 = NEG; v1 = NEG; }
            s_c0[tid] = v0;
            s_c1[tid] = v1;
        }
        __syncthreads();
        if (tid < 256) {
            float m0 = NEG, m1 = NEG;
            #pragma unroll
            for (int dy = -1; dy <= 1; dy++) {
                #pragma unroll
                for (int dx = -1; dx <= 1; dx++) {
                    int q = pp + dy * 18 + dx;
                    m0 = fmaxf(m0, s_c0[q]);
                    m1 = fmaxf(m1, s_c1[q]);
                }
            }
            float v0 = s_c0[pp], v1 = s_c1[pp];
            float k0 = (v0 == m0) ? v0 : 0.f;
            float k1 = (v1 == m1) ? v1 : 0.f;
            if (k0 > best) { best = k0; cat = c0; }
            if (k1 > best) { best = k1; cat = c1; }
        }
        __syncthreads();
    }

    if (tid < 256) {
        int gp = (oy + py - 1) * WW + ox + px - 1;
        g_score[b * HW + gp] = best;
        g_cat[b * HW + gp]   = cat;
    }
}

// =====================================================================
// Kernel 3: top-100. Histogram radix threshold + candidate compaction,
// then single-pass rank-counting selection (keys unique).
// =====================================================================
#define TOPK_SMEM (8192 * 4 + 1024 * 4 + HW * 8)
__global__ __launch_bounds__(1024) void topk_kernel()
{
    extern __shared__ int smi[];
    int* hist = smi;                                     // 8192
    int* suf  = smi + 8192;                              // 1024
    unsigned long long* cand = (unsigned long long*)(smi + 8192 + 1024);
    __shared__ int s_tstar, s_T, s_cnt;

    const int b = blockIdx.x;
    const int tid = threadIdx.x;
    const float* s = g_score + b * HW;

    for (int i = tid; i < 8192; i += 1024) hist[i] = 0;
    if (tid == 0) s_cnt = 0;
    __syncthreads();

    for (int j = tid; j < HW; j += 1024) {
        unsigned int u = __float_as_uint(s[j]);          // scores >= 0
        atomicAdd(&hist[u >> 19], 1);
    }
    __syncthreads();

    int seg = 0;
    #pragma unroll
    for (int k = 0; k < 8; k++) seg += hist[tid * 8 + k];
    suf[tid] = seg;
    __syncthreads();
    for (int off = 1; off < 1024; off <<= 1) {
        int v = suf[tid];
        int add = (tid + off < 1024) ? suf[tid + off] : 0;
        __syncthreads();
        suf[tid] = v + add;
        __syncthreads();
    }
    if (suf[tid] >= KTOP && (tid == 1023 || suf[tid + 1] < KTOP)) s_tstar = tid;
    __syncthreads();
    if (tid == s_tstar) {
        int acc = (tid == 1023) ? 0 : suf[tid + 1];
        for (int bb = tid * 8 + 7; bb >= tid * 8; bb--) {
            acc += hist[bb];
            if (acc >= KTOP) { s_T = bb; break; }
        }
    }
    __syncthreads();
    const int T = s_T;

    for (int j = tid; j < HW; j += 1024) {
        unsigned int u = __float_as_uint(s[j]);
        if ((int)(u >> 19) >= T) {
            int pos = atomicAdd(&s_cnt, 1);
            cand[pos] = ((unsigned long long)u << 32) | (unsigned long long)(HW - j);
        }
    }
    __syncthreads();
    const int N = s_cnt;

    // rank-count selection: rank = #keys strictly greater (keys unique)
    for (int i = tid; i < N; i += 1024) {
        unsigned long long key = cand[i];
        int rank = 0;
        for (int j = 0; j < N; j++) rank += (cand[j] > key);
        if (rank < KTOP) {
            g_tscore[b * KTOP + rank] = __uint_as_float((unsigned int)(key >> 32));
            g_tind[b * KTOP + rank]   = HW - (int)(key & 0xFFFFFFFFull);
        }
    }
}

// =====================================================================
// Kernel 4: recompute reg/wh 3x3 conv at the selected points, 1x1 heads,
// box decode. grid (10, B), 128 threads.
// =====================================================================
__global__ __launch_bounds__(128) void point_kernel(
    const float* __restrict__ x,
    const float* __restrict__ rw1, const float* __restrict__ rb1,
    const float* __restrict__ rw2, const float* __restrict__ rb2,
    const float* __restrict__ ww1, const float* __restrict__ wb1,
    const float* __restrict__ ww2, const float* __restrict__ wb2)
{
    __shared__ float sx[10][576];
    __shared__ int   sp[10];
    __shared__ float sfa[128][11];
    __shared__ float sres[10][4];

    const int g = blockIdx.x, b = blockIdx.y;
    const int tid = threadIdx.x;

    if (tid < 10) sp[tid] = g_tind[b * KTOP + g * 10 + tid];
    __syncthreads();

    for (int e = tid; e < 10 * 576; e += 128) {
        int pt = e / 576;
        int r  = e - pt * 576;
        int c  = r / 9;
        int k9 = r - c * 9;
        int dy = k9 / 3 - 1, dx = k9 % 3 - 1;
        int p = sp[pt];
        int gy = (p >> 7) + dy, gx = (p & 127) + dx;
        float v = 0.f;
        if (gy >= 0 && gy < HH && gx >= 0 && gx < WW)
            v = x[((size_t)b * CINC + c) * HW + gy * WW + gx];
        sx[pt][r] = v;
    }
    __syncthreads();

    const float* wrow = (tid < 64) ? (rw1 + tid * 576) : (ww1 + (tid - 64) * 576);
    float bias = (tid < 64) ? rb1[tid] : wb1[tid - 64];
    float acc[10];
    #pragma unroll
    for (int pt = 0; pt < 10; pt++) acc[pt] = bias;

    for (int j = 0; j < 576; j += 4) {
        float4 w4 = *(const float4*)(wrow + j);
        #pragma unroll
        for (int q = 0; q < 4; q++) {
            float w = (q == 0) ? w4.x : (q == 1) ? w4.y : (q == 2) ? w4.z : w4.w;
            #pragma unroll
            for (int pt = 0; pt < 10; pt++)
                acc[pt] = fmaf(w, sx[pt][j + q], acc[pt]);
        }
    }
    #pragma unroll
    for (int pt = 0; pt < 10; pt++) sfa[tid][pt] = fmaxf(acc[pt], 0.f);
    __syncthreads();

    if (tid < 40) {
        int pt = tid >> 2, o = tid & 3;
        float sv;
        if (o < 2) {
            sv = rb2[o];
            for (int i = 0; i < 64; i++) sv = fmaf(sfa[i][pt], rw2[o * 64 + i], sv);
            sv = 1.f / (1.f + expf(-sv));
        } else {
            int oo = o - 2;
            sv = wb2[oo];
            for (int i = 0; i < 64; i++) sv = fmaf(sfa[64 + i][pt], ww2[oo * 64 + i], sv);
            sv = expf(sv);
        }
        sres[pt][o] = sv;
    }
    __syncthreads();

    if (tid < 10) {
        int p = sp[tid];
        float cx = (float)(p & 127) + sres[tid][0];
        float cy = (float)(p >> 7)  + sres[tid][1];
        float wv = sres[tid][2], hv = sres[tid][3];
        int k = b * KTOP + g * 10 + tid;
        g_boxes[k * 4 + 0] = (cx - wv * 0.5f) * 4.f;
        g_boxes[k * 4 + 1] = (cy - hv * 0.5f) * 4.f;
        g_boxes[k * 4 + 2] = (cx + wv * 0.5f) * 4.f;
        g_boxes[k * 4 + 3] = (cy + hv * 0.5f) * 4.f;
    }
}

// =====================================================================
// Kernel 5: greedy NMS + output assembly
// =====================================================================
__global__ __launch_bounds__(128) void nms_kernel(float* __restrict__ out)
{
    const int b = blockIdx.x;
    const int tid = threadIdx.x;
    __shared__ float bx[KTOP][4];
    __shared__ float barea[KTOP];
    __shared__ int keep[KTOP];

    float score = 0.f; int cat = 0;
    if (tid < KTOP) {
        int k = b * KTOP + tid;
        score = g_tscore[k];
        cat   = g_cat[b * HW + g_tind[k]];
        float x1 = g_boxes[k * 4 + 0], y1 = g_boxes[k * 4 + 1];
        float x2 = g_boxes[k * 4 + 2], y2 = g_boxes[k * 4 + 3];
        bx[tid][0] = x1; bx[tid][1] = y1; bx[tid][2] = x2; bx[tid][3] = y2;
        barea[tid] = (x2 - x1) * (y2 - y1);
        keep[tid] = (score > 0.2f) ? 1 : 0;
    }
    __syncthreads();

    for (int i = 0; i < KTOP - 1; i++) {
        if (tid < KTOP && tid > i && keep[i]) {
            float xx1 = fmaxf(bx[i][0], bx[tid][0]);
            float yy1 = fmaxf(bx[i][1], bx[tid][1]);
            float xx2 = fminf(bx[i][2], bx[tid][2]);
            float yy2 = fminf(bx[i][3], bx[tid][3]);
            float iw = fmaxf(xx2 - xx1, 0.f);
            float ih = fmaxf(yy2 - yy1, 0.f);
            float inter = iw * ih;
            float iou = inter / (barea[i] + barea[tid] - inter + 1e-9f);
            if (iou > 0.5f) keep[tid] = 0;
        }
        __syncthreads();
    }

    if (tid < KTOP) {
        int base = b * KTOP + tid;
        out[base * 4 + 0] = bx[tid][0];
        out[base * 4 + 1] = bx[tid][1];
        out[base * 4 + 2] = bx[tid][2];
        out[base * 4 + 3] = bx[tid][3];
        out[6400 + base] = (float)cat;
        out[8000 + base] = score;
        out[9600 + base] = keep[tid] ? 1.f : 0.f;
    }
}

// =====================================================================
extern "C" void kernel_launch(void* const* d_in, const int* in_sizes, int n_in,
                              void* d_out, int out_size)
{
    const float* x      = (const float*)d_in[0];
    const float* cls_w1 = (const float*)d_in[1];
    const float* cls_b1 = (const float*)d_in[2];
    const float* cls_w2 = (const float*)d_in[3];
    const float* cls_b2 = (const float*)d_in[4];
    const float* reg_w1 = (const float*)d_in[5];
    const float* reg_b1 = (const float*)d_in[6];
    const float* reg_w2 = (const float*)d_in[7];
    const float* reg_b2 = (const float*)d_in[8];
    const float* wh_w1  = (const float*)d_in[9];
    const float* wh_b1  = (const float*)d_in[10];
    const float* wh_w2  = (const float*)d_in[11];
    const float* wh_b2  = (const float*)d_in[12];
    float* out = (float*)d_out;

    cudaFuncSetAttribute(conv1_kernel, cudaFuncAttributeMaxDynamicSharedMemorySize, CONV1_SMEM);
    cudaFuncSetAttribute(topk_kernel, cudaFuncAttributeMaxDynamicSharedMemorySize, TOPK_SMEM);

    conv1_kernel<<<dim3(8, 8, BATCH), 256, CONV1_SMEM>>>(x, cls_w1, cls_b1);
    clspeak_kernel<<<dim3(8, 8, BATCH), 352>>>(cls_w2, cls_b2);
    topk_kernel<<<BATCH, 1024, TOPK_SMEM>>>();
    point_kernel<<<dim3(10, BATCH), 128>>>(x, reg_w1, reg_b1, reg_w2, reg_b2,
                                           wh_w1, wh_b1, wh_w2, wh_b2);
    nms_kernel<<<BATCH, 128>>>(out);
}

// round 4
// speedup vs baseline: 3.4582x; 1.0208x over previous
#include <cuda_runtime.h>
#include <math.h>

#define BATCH 16
#define CINC 64
#define HH 128
#define WW 128
#define HW 16384
#define NCLS 80
#define KTOP 100

// ---------------- device scratch ----------------
__device__ float g_featc[BATCH * 64 * HW];   // relu(conv3x3) cls branch only
__device__ float g_score[BATCH * HW];
__device__ int   g_cat  [BATCH * HW];
__device__ float g_tscore[BATCH * KTOP];
__device__ int   g_tind  [BATCH * KTOP];
__device__ float g_boxes[BATCH * KTOP * 4];

// ---------------- f32x2 helpers ----------------
__device__ __forceinline__ unsigned long long pk2(float lo, float hi) {
    unsigned long long r;
    asm("mov.b64 %0, {%1, %2};" : "=l"(r) : "r"(__float_as_uint(lo)), "r"(__float_as_uint(hi)));
    return r;
}
__device__ __forceinline__ unsigned long long dup2(float x) { return pk2(x, x); }
__device__ __forceinline__ unsigned long long fma2(unsigned long long a, unsigned long long b,
                                                   unsigned long long c) {
    unsigned long long d;
    asm("fma.rn.f32x2 %0, %1, %2, %3;" : "=l"(d) : "l"(a), "l"(b), "l"(c));
    return d;
}
__device__ __forceinline__ float2 upk(unsigned long long v) {
    unsigned int a, b;
    asm("mov.b64 {%0, %1}, %2;" : "=r"(a), "=r"(b) : "l"(v));
    return make_float2(__uint_as_float(a), __uint_as_float(b));
}

// =====================================================================
// Kernel 1: 3x3 conv (64 -> 64, cls branch only) + bias + relu, f32x2.
// =====================================================================
#define SIN_WORDS (64 * 18 * 20)
#define SW_WORDS  (64 * 9 * 36)
#define CONV1_SMEM ((SIN_WORDS + SW_WORDS) * 4)

__global__ __launch_bounds__(256, 1) void conv1_kernel(
    const float* __restrict__ x,
    const float* __restrict__ w1, const float* __restrict__ b1)
{
    extern __shared__ float sm[];
    float* s_in = sm;
    float* s_w  = sm + SIN_WORDS;

    const int tx = blockIdx.x, ty = blockIdx.y, b = blockIdx.z;
    const int ox = tx * 16, oy = ty * 16;
    const int tid = threadIdx.x;
    const float* xb = x + (size_t)b * CINC * HW;

    for (int e = tid; e < 64 * 324; e += 256) {
        int c   = e / 324;
        int rem = e - c * 324;
        int iy  = rem / 18;
        int ix  = rem - iy * 18;
        int gy = oy + iy - 1, gx = ox + ix - 1;
        float v = 0.f;
        if (gy >= 0 && gy < HH && gx >= 0 && gx < WW)
            v = xb[c * HW + gy * WW + gx];
        s_in[c * 360 + iy * 20 + ix] = v;
    }

    const int ocg = tid >> 5;
    const int r   = tid & 31;
    const int ly  = r >> 1;
    const int lx0 = (r & 1) * 8;

    float* fout = g_featc + (size_t)b * 64 * HW;

    for (int chunk = 0; chunk < 2; chunk++) {
        const int oc_base = chunk * 32;
        __syncthreads();
        for (int e = tid; e < 32 * 576; e += 256) {
            int o   = e / 576;
            int rem = e - o * 576;
            s_w[rem * 36 + o] = w1[(oc_base + o) * 576 + rem];
        }
        __syncthreads();

        unsigned long long acc01[8], acc23[8];
        #pragma unroll
        for (int p = 0; p < 8; p++) { acc01[p] = 0ull; acc23[p] = 0ull; }

        for (int cin = 0; cin < 64; cin++) {
            const float* si  = s_in + cin * 360 + ly * 20 + lx0;
            const float* swc = s_w + cin * 9 * 36 + ocg * 4;
            #pragma unroll
            for (int ky = 0; ky < 3; ky++) {
                const float* row = si + ky * 20;
                float4 va = *(const float4*)(row);
                float4 vb = *(const float4*)(row + 4);
                float2 vc = *(const float2*)(row + 8);
                unsigned long long d[10];
                d[0]=dup2(va.x); d[1]=dup2(va.y); d[2]=dup2(va.z); d[3]=dup2(va.w);
                d[4]=dup2(vb.x); d[5]=dup2(vb.y); d[6]=dup2(vb.z); d[7]=dup2(vb.w);
                d[8]=dup2(vc.x); d[9]=dup2(vc.y);
                #pragma unroll
                for (int kx = 0; kx < 3; kx++) {
                    ulonglong2 wv = *(const ulonglong2*)(swc + (ky * 3 + kx) * 36);
                    #pragma unroll
                    for (int p = 0; p < 8; p++) {
                        acc01[p] = fma2(d[p + kx], wv.x, acc01[p]);
                        acc23[p] = fma2(d[p + kx], wv.y, acc23[p]);
                    }
                }
            }
        }

        float rr[4][8];
        #pragma unroll
        for (int p = 0; p < 8; p++) {
            float2 a = upk(acc01[p]);
            float2 c = upk(acc23[p]);
            rr[0][p] = a.x; rr[1][p] = a.y; rr[2][p] = c.x; rr[3][p] = c.y;
        }
        #pragma unroll
        for (int i = 0; i < 4; i++) {
            int oc = oc_base + ocg * 4 + i;
            float bias = b1[oc];
            float* op = fout + (size_t)oc * HW + (oy + ly) * WW + ox + lx0;
            float4 v0, v1;
            v0.x = fmaxf(rr[i][0] + bias, 0.f); v0.y = fmaxf(rr[i][1] + bias, 0.f);
            v0.z = fmaxf(rr[i][2] + bias, 0.f); v0.w = fmaxf(rr[i][3] + bias, 0.f);
            v1.x = fmaxf(rr[i][4] + bias, 0.f); v1.y = fmaxf(rr[i][5] + bias, 0.f);
            v1.z = fmaxf(rr[i][6] + bias, 0.f); v1.w = fmaxf(rr[i][7] + bias, 0.f);
            *(float4*)(op)     = v0;
            *(float4*)(op + 4) = v1;
        }
    }
}

// =====================================================================
// Kernel 2 (fused): 1x1 conv (64->80) + sigmoid + 3x3 peak + argmax.
// Grouped: 4 groups x 20 classes; only 8 __syncthreads total.
// 352 threads; tid<324 computes one halo px (feat cached in regs as
// 32 channel-pairs); tid<256 pools the inner 16x16.
// =====================================================================
#define CLS_STRIDE 328
__global__ __launch_bounds__(352, 1) void clspeak_kernel(
    const float* __restrict__ w2, const float* __restrict__ b2)
{
    __shared__ float s_w[80 * 64];
    __shared__ float s_b[80];
    __shared__ float s_cls[20 * CLS_STRIDE];

    const int tx = blockIdx.x, ty = blockIdx.y, b = blockIdx.z;
    const int ox = tx * 16, oy = ty * 16;
    const int tid = threadIdx.x;
    const float NEG = -1e30f;

    for (int e = tid; e < 80 * 64; e += 352) s_w[e] = w2[e];
    if (tid < 80) s_b[tid] = b2[tid];

    unsigned long long fd[32];
    bool inimg = false;
    if (tid < 324) {
        int iy = tid / 18, ix = tid - iy * 18;
        int gy = oy + iy - 1, gx = ox + ix - 1;
        inimg = (gy >= 0 && gy < HH && gx >= 0 && gx < WW);
        const float* fp = g_featc + (size_t)b * 64 * HW + gy * WW + gx;
        #pragma unroll
        for (int i = 0; i < 32; i++) {
            float a = inimg ? fp[(2 * i) * HW]     : 0.f;
            float c = inimg ? fp[(2 * i + 1) * HW] : 0.f;
            fd[i] = pk2(a, c);
        }
    }
    __syncthreads();

    const int py = (tid >> 4) + 1, px = (tid & 15) + 1;
    const int pp = py * 18 + px;
    float best = -1.f;
    int cat = 0;

    for (int g = 0; g < 4; g++) {
        if (tid < 324) {
            #pragma unroll
            for (int cp = 0; cp < 10; cp++) {
                const int c0 = g * 20 + 2 * cp;
                unsigned long long a0 = 0ull, a1 = 0ull;
                const ulonglong2* w0 = (const ulonglong2*)(s_w + c0 * 64);
                const ulonglong2* w1 = (const ulonglong2*)(s_w + (c0 + 1) * 64);
                #pragma unroll
                for (int i = 0; i < 16; i++) {
                    ulonglong2 wa = w0[i];
                    ulonglong2 wb = w1[i];
                    a0 = fma2(fd[2 * i],     wa.x, a0);
                    a0 = fma2(fd[2 * i + 1], wa.y, a0);
                    a1 = fma2(fd[2 * i],     wb.x, a1);
                    a1 = fma2(fd[2 * i + 1], wb.y, a1);
                }
                float2 u0 = upk(a0), u1 = upk(a1);
                float v0 = u0.x + u0.y + s_b[c0];
                float v1 = u1.x + u1.y + s_b[c0 + 1];
                v0 = 1.f / (1.f + expf(-v0));
                v1 = 1.f / (1.f + expf(-v1));
                if (!inimg) { v0 = NEG; v1 = NEG; }
                s_cls[(2 * cp)     * CLS_STRIDE + tid] = v0;
                s_cls[(2 * cp + 1) * CLS_STRIDE + tid] = v1;
            }
        }
        __syncthreads();
        if (tid < 256) {
            #pragma unroll 4
            for (int c = 0; c < 20; c++) {
                const float* row = s_cls + c * CLS_STRIDE;
                float v = row[pp];
                float m = v;
                m = fmaxf(m, row[pp - 19]); m = fmaxf(m, row[pp - 18]); m = fmaxf(m, row[pp - 17]);
                m = fmaxf(m, row[pp - 1]);                               m = fmaxf(m, row[pp + 1]);
                m = fmaxf(m, row[pp + 17]); m = fmaxf(m, row[pp + 18]); m = fmaxf(m, row[pp + 19]);
                float k = (v == m) ? v : 0.f;
                if (k > best) { best = k; cat = g * 20 + c; }
            }
        }
        __syncthreads();
    }

    if (tid < 256) {
        int gp = (oy + py - 1) * WW + ox + px - 1;
        g_score[b * HW + gp] = best;
        g_cat[b * HW + gp]   = cat;
    }
}

// =====================================================================
// Kernel 3: top-100. Histogram radix threshold + compaction + rank-count.
// =====================================================================
#define TOPK_SMEM (8192 * 4 + 1024 * 4 + HW * 8)
__global__ __launch_bounds__(1024) void topk_kernel()
{
    extern __shared__ int smi[];
    int* hist = smi;
    int* suf  = smi + 8192;
    unsigned long long* cand = (unsigned long long*)(smi + 8192 + 1024);
    __shared__ int s_tstar, s_T, s_cnt;

    const int b = blockIdx.x;
    const int tid = threadIdx.x;
    const float* s = g_score + b * HW;

    for (int i = tid; i < 8192; i += 1024) hist[i] = 0;
    if (tid == 0) s_cnt = 0;
    __syncthreads();

    for (int j = tid; j < HW; j += 1024) {
        unsigned int u = __float_as_uint(s[j]);
        atomicAdd(&hist[u >> 19], 1);
    }
    __syncthreads();

    int seg = 0;
    #pragma unroll
    for (int k = 0; k < 8; k++) seg += hist[tid * 8 + k];
    suf[tid] = seg;
    __syncthreads();
    for (int off = 1; off < 1024; off <<= 1) {
        int v = suf[tid];
        int add = (tid + off < 1024) ? suf[tid + off] : 0;
        __syncthreads();
        suf[tid] = v + add;
        __syncthreads();
    }
    if (suf[tid] >= KTOP && (tid == 1023 || suf[tid + 1] < KTOP)) s_tstar = tid;
    __syncthreads();
    if (tid == s_tstar) {
        int acc = (tid == 1023) ? 0 : suf[tid + 1];
        for (int bb = tid * 8 + 7; bb >= tid * 8; bb--) {
            acc += hist[bb];
            if (acc >= KTOP) { s_T = bb; break; }
        }
    }
    __syncthreads();
    const int T = s_T;

    for (int j = tid; j < HW; j += 1024) {
        unsigned int u = __float_as_uint(s[j]);
        if ((int)(u >> 19) >= T) {
            int pos = atomicAdd(&s_cnt, 1);
            cand[pos] = ((unsigned long long)u << 32) | (unsigned long long)(HW - j);
        }
    }
    __syncthreads();
    const int N = s_cnt;

    for (int i = tid; i < N; i += 1024) {
        unsigned long long key = cand[i];
        int rank = 0;
        for (int j = 0; j < N; j++) rank += (cand[j] > key);
        if (rank < KTOP) {
            g_tscore[b * KTOP + rank] = __uint_as_float((unsigned int)(key >> 32));
            g_tind[b * KTOP + rank]   = HW - (int)(key & 0xFFFFFFFFull);
        }
    }
}

// =====================================================================
// Kernel 4: recompute reg/wh 3x3 conv at selected points + 1x1 heads +
// box decode. grid (20, B), 128 threads, 5 points/block.
// =====================================================================
#define PTS 5
__global__ __launch_bounds__(128) void point_kernel(
    const float* __restrict__ x,
    const float* __restrict__ rw1, const float* __restrict__ rb1,
    const float* __restrict__ rw2, const float* __restrict__ rb2,
    const float* __restrict__ ww1, const float* __restrict__ wb1,
    const float* __restrict__ ww2, const float* __restrict__ wb2)
{
    __shared__ float sx[PTS][576];
    __shared__ int   sp[PTS];
    __shared__ float sfa[128][PTS + 1];
    __shared__ float sres[PTS][4];

    const int g = blockIdx.x, b = blockIdx.y;
    const int tid = threadIdx.x;

    if (tid < PTS) sp[tid] = g_tind[b * KTOP + g * PTS + tid];
    __syncthreads();

    for (int e = tid; e < PTS * 576; e += 128) {
        int pt = e / 576;
        int r  = e - pt * 576;
        int c  = r / 9;
        int k9 = r - c * 9;
        int dy = k9 / 3 - 1, dx = k9 % 3 - 1;
        int p = sp[pt];
        int gy = (p >> 7) + dy, gx = (p & 127) + dx;
        float v = 0.f;
        if (gy >= 0 && gy < HH && gx >= 0 && gx < WW)
            v = x[((size_t)b * CINC + c) * HW + gy * WW + gx];
        sx[pt][r] = v;
    }
    __syncthreads();

    const float* wrow = (tid < 64) ? (rw1 + tid * 576) : (ww1 + (tid - 64) * 576);
    float bias = (tid < 64) ? rb1[tid] : wb1[tid - 64];
    float acc[PTS];
    #pragma unroll
    for (int pt = 0; pt < PTS; pt++) acc[pt] = bias;

    for (int j = 0; j < 576; j += 4) {
        float4 w4 = *(const float4*)(wrow + j);
        #pragma unroll
        for (int q = 0; q < 4; q++) {
            float w = (q == 0) ? w4.x : (q == 1) ? w4.y : (q == 2) ? w4.z : w4.w;
            #pragma unroll
            for (int pt = 0; pt < PTS; pt++)
                acc[pt] = fmaf(w, sx[pt][j + q], acc[pt]);
        }
    }
    #pragma unroll
    for (int pt = 0; pt < PTS; pt++) sfa[tid][pt] = fmaxf(acc[pt], 0.f);
    __syncthreads();

    if (tid < PTS * 4) {
        int pt = tid >> 2, o = tid & 3;
        float sv;
        if (o < 2) {
            sv = rb2[o];
            for (int i = 0; i < 64; i++) sv = fmaf(sfa[i][pt], rw2[o * 64 + i], sv);
            sv = 1.f / (1.f + expf(-sv));
        } else {
            int oo = o - 2;
            sv = wb2[oo];
            for (int i = 0; i < 64; i++) sv = fmaf(sfa[64 + i][pt], ww2[oo * 64 + i], sv);
            sv = expf(sv);
        }
        sres[pt][o] = sv;
    }
    __syncthreads();

    if (tid < PTS) {
        int p = sp[tid];
        float cx = (float)(p & 127) + sres[tid][0];
        float cy = (float)(p >> 7)  + sres[tid][1];
        float wv = sres[tid][2], hv = sres[tid][3];
        int k = b * KTOP + g * PTS + tid;
        g_boxes[k * 4 + 0] = (cx - wv * 0.5f) * 4.f;
        g_boxes[k * 4 + 1] = (cy - hv * 0.5f) * 4.f;
        g_boxes[k * 4 + 2] = (cx + wv * 0.5f) * 4.f;
        g_boxes[k * 4 + 3] = (cy + hv * 0.5f) * 4.f;
    }
}

// =====================================================================
// Kernel 5: greedy NMS + output assembly
// =====================================================================
__global__ __launch_bounds__(128) void nms_kernel(float* __restrict__ out)
{
    const int b = blockIdx.x;
    const int tid = threadIdx.x;
    __shared__ float bx[KTOP][4];
    __shared__ float barea[KTOP];
    __shared__ int keep[KTOP];

    float score = 0.f; int cat = 0;
    if (tid < KTOP) {
        int k = b * KTOP + tid;
        score = g_tscore[k];
        cat   = g_cat[b * HW + g_tind[k]];
        float x1 = g_boxes[k * 4 + 0], y1 = g_boxes[k * 4 + 1];
        float x2 = g_boxes[k * 4 + 2], y2 = g_boxes[k * 4 + 3];
        bx[tid][0] = x1; bx[tid][1] = y1; bx[tid][2] = x2; bx[tid][3] = y2;
        barea[tid] = (x2 - x1) * (y2 - y1);
        keep[tid] = (score > 0.2f) ? 1 : 0;
    }
    __syncthreads();

    for (int i = 0; i < KTOP - 1; i++) {
        if (tid < KTOP && tid > i && keep[i]) {
            float xx1 = fmaxf(bx[i][0], bx[tid][0]);
            float yy1 = fmaxf(bx[i][1], bx[tid][1]);
            float xx2 = fminf(bx[i][2], bx[tid][2]);
            float yy2 = fminf(bx[i][3], bx[tid][3]);
            float iw = fmaxf(xx2 - xx1, 0.f);
            float ih = fmaxf(yy2 - yy1, 0.f);
            float inter = iw * ih;
            float iou = inter / (barea[i] + barea[tid] - inter + 1e-9f);
            if (iou > 0.5f) keep[tid] = 0;
        }
        __syncthreads();
    }

    if (tid < KTOP) {
        int base = b * KTOP + tid;
        out[base * 4 + 0] = bx[tid][0];
        out[base * 4 + 1] = bx[tid][1];
        out[base * 4 + 2] = bx[tid][2];
        out[base * 4 + 3] = bx[tid][3];
        out[6400 + base] = (float)cat;
        out[8000 + base] = score;
        out[9600 + base] = keep[tid] ? 1.f : 0.f;
    }
}

// =====================================================================
extern "C" void kernel_launch(void* const* d_in, const int* in_sizes, int n_in,
                              void* d_out, int out_size)
{
    const float* x      = (const float*)d_in[0];
    const float* cls_w1 = (const float*)d_in[1];
    const float* cls_b1 = (const float*)d_in[2];
    const float* cls_w2 = (const float*)d_in[3];
    const float* cls_b2 = (const float*)d_in[4];
    const float* reg_w1 = (const float*)d_in[5];
    const float* reg_b1 = (const float*)d_in[6];
    const float* reg_w2 = (const float*)d_in[7];
    const float* reg_b2 = (const float*)d_in[8];
    const float* wh_w1  = (const float*)d_in[9];
    const float* wh_b1  = (const float*)d_in[10];
    const float* wh_w2  = (const float*)d_in[11];
    const float* wh_b2  = (const float*)d_in[12];
    float* out = (float*)d_out;

    cudaFuncSetAttribute(conv1_kernel, cudaFuncAttributeMaxDynamicSharedMemorySize, CONV1_SMEM);
    cudaFuncSetAttribute(topk_kernel, cudaFuncAttributeMaxDynamicSharedMemorySize, TOPK_SMEM);

    conv1_kernel<<<dim3(8, 8, BATCH), 256, CONV1_SMEM>>>(x, cls_w1, cls_b1);
    clspeak_kernel<<<dim3(8, 8, BATCH), 352>>>(cls_w2, cls_b2);
    topk_kernel<<<BATCH, 1024, TOPK_SMEM>>>();
    point_kernel<<<dim3(20, BATCH), 128>>>(x, reg_w1, reg_b1, reg_w2, reg_b2,
                                           wh_w1, wh_b1, wh_w2, wh_b2);
    nms_kernel<<<BATCH, 128>>>(out);
}